// round 9
// baseline (speedup 1.0000x reference)
#include <cuda_runtime.h>

typedef unsigned long long u64;

#define B_  512
#define T_  512
#define F_  13
#define H_  128
#define NT  256

// 134MB scratch: xp[(b*T + t)*H + j] = x@W_ih^T + b_ih + b_hh
__device__ float g_xp[(size_t)B_ * T_ * H_];

__device__ __forceinline__ u64 fma2(u64 a, u64 b, u64 c) {
    u64 d;
    asm("fma.rn.f32x2 %0, %1, %2, %3;" : "=l"(d) : "l"(a), "l"(b), "l"(c));
    return d;
}
__device__ __forceinline__ float f2sum(u64 a) {
    float lo, hi;
    asm("mov.b64 {%0, %1}, %2;" : "=f"(lo), "=f"(hi) : "l"(a));
    return lo + hi;
}
// tanh(x) = 1 - 2/(1+e^{2x}); abs err ~1e-7, inf-safe.
__device__ __forceinline__ float tanh_fast(float x) {
    float e = __expf(2.f * x);
    return 1.f - __fdividef(2.f, 1.f + e);
}
__device__ __forceinline__ float sigmoid_fast(float s) {
    return __fdividef(1.f, 1.f + __expf(-s));
}

// ---------------------------------------------------------------------------
// Kernel 1: xp precompute. Block = 256 threads handles 256 (b,t) rows.
// Thread (j = tid&127, half = tid>>7) computes 128 rows for output j.
// x rows staged in smem (broadcast reads); STG coalesced over j.
// ---------------------------------------------------------------------------
__global__ void __launch_bounds__(256, 2) xp_kernel(
    const float* __restrict__ x,
    const float* __restrict__ W_ih,
    const float* __restrict__ b_ih,
    const float* __restrict__ b_hh)
{
    __shared__ float xs[256 * 14];
    const int tid = threadIdx.x;
    const size_t rowbase = (size_t)blockIdx.x * 256;

    for (int i = tid; i < 256 * F_; i += 256) {
        int r = i / F_, f = i - r * F_;
        xs[r * 14 + f] = x[rowbase * F_ + i];
    }
    __syncthreads();

    const int j    = tid & 127;
    const int half = tid >> 7;
    float w[F_];
#pragma unroll
    for (int f = 0; f < F_; f++) w[f] = __ldg(W_ih + j * F_ + f);
    const float bias = __ldg(b_ih + j) + __ldg(b_hh + j);

    const int r0 = half * 128;
    for (int r = 0; r < 128; r++) {
        const float* xr = xs + (r0 + r) * 14;
        float acc = bias;
#pragma unroll
        for (int f = 0; f < F_; f++) acc = fmaf(xr[f], w[f], acc);
        g_xp[(rowbase + r0 + r) * H_ + j] = acc;
    }
}

// ---------------------------------------------------------------------------
// Kernel 2: fused persistent scan + fc head.
// 128 CTAs x 256 threads, 4 batch rows per CTA, ONE __syncthreads per step.
// Rec (tid 0..127): thread (jj = tid>>1, kh = tid&1) holds W_hh rows
//   {jj, jj+64} over k-half [64kh,+64) (32 u64 regs). Each 16B h-load feeds
//   2 j-rows (LDS:fma2 = 1:4). xp terms register-prefetched with distance-2
//   LDG. Cross-k partials merge via shfl_xor(1); tanh; STS into Hs[cur^1].
// FC (tid 128..255): as R8 — thread (kh2 = ft&1, oo = (ft>>1)&31, rp = ft>>6)
//   holds fc1_w rows {oo, oo+32} over k-half; processes h(t) = Hs[cur] for
//   rows {2rp, 2rp+1}; k-merge shfl, relu*fc2_w, bfly over offs 2..16;
//   lane0 -> red[cur^1]; 4 threads emit sigmoid one iteration later.
// ---------------------------------------------------------------------------
__global__ void __launch_bounds__(NT, 1) rnn_fused(
    const float* __restrict__ W_hh,
    const float* __restrict__ fc1_w,
    const float* __restrict__ fc1_b,
    const float* __restrict__ fc2_w,
    const float* __restrict__ fc2_b,
    float* __restrict__ out)
{
    __shared__ __align__(16) float Hs[2][4 * H_];   // double-buffered h
    __shared__ float2 red[2][2][2];                 // [buf][rp][oohigh]

    const int tid  = threadIdx.x;
    const int row0 = blockIdx.x * 4;

    for (int i = tid; i < 2 * 4 * H_; i += NT) ((float*)Hs)[i] = 0.f;
    __syncthreads();

    int cur = 0;

    if (tid < 128) {
        // =================== RECURRENCE ===================
        const int jj   = tid >> 1;       // j rows {jj, jj+64}
        const int kh   = tid & 1;        // k-half
        const int koff = kh * 64;
        const int r0   = 2 * kh,     r1 = 2 * kh + 1;   // owned batch rows
        const int o0   = 2 - 2 * kh, o1 = 3 - 2 * kh;   // partner's rows

        u64 wA[32], wB[32];
        {
            const ulonglong2* ra =
                (const ulonglong2*)(W_hh + (size_t)jj * H_ + koff);
            const ulonglong2* rb =
                (const ulonglong2*)(W_hh + (size_t)(jj + 64) * H_ + koff);
#pragma unroll
            for (int m = 0; m < 16; m++) {
                ulonglong2 va = ra[m], vb = rb[m];
                wA[2 * m] = va.x; wA[2 * m + 1] = va.y;
                wB[2 * m] = vb.x; wB[2 * m + 1] = vb.y;
            }
        }

        // xp pointers for (row r0/r1, j jj/jj+64); advanced by H_ per step
        const float* pA0 = g_xp + ((size_t)(row0 + r0) * T_) * H_ + jj;
        const float* pA1 = g_xp + ((size_t)(row0 + r1) * T_) * H_ + jj;
        const float* pB0 = pA0 + 64;
        const float* pB1 = pA1 + 64;

        // distance-2 prefetch pipeline: xc = xp(t), xn = xp(t+1)
        float xcA0 = __ldg(pA0), xcA1 = __ldg(pA1);
        float xcB0 = __ldg(pB0), xcB1 = __ldg(pB1);
        float xnA0 = __ldg(pA0 + H_), xnA1 = __ldg(pA1 + H_);
        float xnB0 = __ldg(pB0 + H_), xnB1 = __ldg(pB1 + H_);
        pA0 += 2 * H_; pA1 += 2 * H_; pB0 += 2 * H_; pB1 += 2 * H_;

        for (int t = 0; t <= T_; t++) {
            if (t < T_) {
                // prefetch xp(t+2)
                float xqA0 = 0.f, xqA1 = 0.f, xqB0 = 0.f, xqB1 = 0.f;
                if (t + 2 < T_) {
                    xqA0 = __ldg(pA0); xqA1 = __ldg(pA1);
                    xqB0 = __ldg(pB0); xqB1 = __ldg(pB1);
                    pA0 += H_; pA1 += H_; pB0 += H_; pB1 += H_;
                }

                const float* Hrd = Hs[cur];
                float*       Hwr = Hs[cur ^ 1];

                u64 aA[4], aB[4];
#pragma unroll
                for (int r = 0; r < 4; r++) { aA[r] = 0ull; aB[r] = 0ull; }

#pragma unroll
                for (int m = 0; m < 16; m++) {
                    ulonglong2 h0 = *(const ulonglong2*)(Hrd + 0 * H_ + koff + 4 * m);
                    ulonglong2 h1 = *(const ulonglong2*)(Hrd + 1 * H_ + koff + 4 * m);
                    ulonglong2 h2 = *(const ulonglong2*)(Hrd + 2 * H_ + koff + 4 * m);
                    ulonglong2 h3 = *(const ulonglong2*)(Hrd + 3 * H_ + koff + 4 * m);
                    aA[0] = fma2(h0.x, wA[2 * m], aA[0]);
                    aA[1] = fma2(h1.x, wA[2 * m], aA[1]);
                    aA[2] = fma2(h2.x, wA[2 * m], aA[2]);
                    aA[3] = fma2(h3.x, wA[2 * m], aA[3]);
                    aB[0] = fma2(h0.x, wB[2 * m], aB[0]);
                    aB[1] = fma2(h1.x, wB[2 * m], aB[1]);
                    aB[2] = fma2(h2.x, wB[2 * m], aB[2]);
                    aB[3] = fma2(h3.x, wB[2 * m], aB[3]);
                    aA[0] = fma2(h0.y, wA[2 * m + 1], aA[0]);
                    aA[1] = fma2(h1.y, wA[2 * m + 1], aA[1]);
                    aA[2] = fma2(h2.y, wA[2 * m + 1], aA[2]);
                    aA[3] = fma2(h3.y, wA[2 * m + 1], aA[3]);
                    aB[0] = fma2(h0.y, wB[2 * m + 1], aB[0]);
                    aB[1] = fma2(h1.y, wB[2 * m + 1], aB[1]);
                    aB[2] = fma2(h2.y, wB[2 * m + 1], aB[2]);
                    aB[3] = fma2(h3.y, wB[2 * m + 1], aB[3]);
                }

                float pA0s = f2sum(aA[r0]), pA1s = f2sum(aA[r1]);
                float pB0s = f2sum(aB[r0]), pB1s = f2sum(aB[r1]);
                float qA0 = f2sum(aA[o0]), qA1 = f2sum(aA[o1]);
                float qB0 = f2sum(aB[o0]), qB1 = f2sum(aB[o1]);
                // partner (lane^1) holds the other k-half of MY rows
                float eA0 = __shfl_xor_sync(0xffffffffu, qA0, 1);
                float eA1 = __shfl_xor_sync(0xffffffffu, qA1, 1);
                float eB0 = __shfl_xor_sync(0xffffffffu, qB0, 1);
                float eB1 = __shfl_xor_sync(0xffffffffu, qB1, 1);

                Hwr[r0 * H_ + jj]      = tanh_fast(pA0s + eA0 + xcA0);
                Hwr[r1 * H_ + jj]      = tanh_fast(pA1s + eA1 + xcA1);
                Hwr[r0 * H_ + jj + 64] = tanh_fast(pB0s + eB0 + xcB0);
                Hwr[r1 * H_ + jj + 64] = tanh_fast(pB1s + eB1 + xcB1);

                // rotate prefetch pipeline
                xcA0 = xnA0; xcA1 = xnA1; xcB0 = xnB0; xcB1 = xnB1;
                xnA0 = xqA0; xnA1 = xqA1; xnB0 = xqB0; xnB1 = xqB1;
            }
            __syncthreads();
            cur ^= 1;
        }
    } else {
        // =================== FC HEAD ===================
        const int ft    = tid - 128;
        const int oo    = (ft >> 1) & 31;  // o rows {oo, oo+32}
        const int rp    = ft >> 6;         // batch rows {2rp, 2rp+1}
        const int lane  = ft & 31;
        const int ooh   = (ft >> 5) & 1;
        const int koff2 = (ft & 1) * 64;

        u64 fwA[32], fwB[32];
        {
            const ulonglong2* ra =
                (const ulonglong2*)(fc1_w + (size_t)oo * H_ + koff2);
            const ulonglong2* rb =
                (const ulonglong2*)(fc1_w + (size_t)(oo + 32) * H_ + koff2);
#pragma unroll
            for (int m = 0; m < 16; m++) {
                ulonglong2 va = ra[m], vb = rb[m];
                fwA[2 * m] = va.x; fwA[2 * m + 1] = va.y;
                fwB[2 * m] = vb.x; fwB[2 * m + 1] = vb.y;
            }
        }
        const float b1A = __ldg(fc1_b + oo);
        const float b1B = __ldg(fc1_b + oo + 32);
        const float w2A = __ldg(fc2_w + oo);
        const float w2B = __ldg(fc2_w + oo + 32);
        const float b2  = __ldg(fc2_b);

        for (int t = 0; t <= T_; t++) {
            if (t >= 2 && ft < 4) {
                const int r = ft;
                float2 v0 = red[cur][r >> 1][0];
                float2 v1 = red[cur][r >> 1][1];
                float s = (r & 1) ? (v0.y + v1.y) : (v0.x + v1.x);
                out[(size_t)(row0 + r) * T_ + (t - 2)] = sigmoid_fast(s + b2);
            }

            if (t >= 1) {
                const float* Hrd = Hs[cur];      // h(t)
                const float* h0p = Hrd + (2 * rp) * H_ + koff2;
                const float* h1p = Hrd + (2 * rp + 1) * H_ + koff2;

                u64 q00 = 0ull, q01 = 0ull, q10 = 0ull, q11 = 0ull;
#pragma unroll
                for (int m = 0; m < 16; m++) {
                    ulonglong2 hv0 = *(const ulonglong2*)(h0p + 4 * m);
                    ulonglong2 hv1 = *(const ulonglong2*)(h1p + 4 * m);
                    q00 = fma2(hv0.x, fwA[2 * m], q00);
                    q01 = fma2(hv0.x, fwB[2 * m], q01);
                    q10 = fma2(hv1.x, fwA[2 * m], q10);
                    q11 = fma2(hv1.x, fwB[2 * m], q11);
                    q00 = fma2(hv0.y, fwA[2 * m + 1], q00);
                    q01 = fma2(hv0.y, fwB[2 * m + 1], q01);
                    q10 = fma2(hv1.y, fwA[2 * m + 1], q10);
                    q11 = fma2(hv1.y, fwB[2 * m + 1], q11);
                }
                float d00 = f2sum(q00), d01 = f2sum(q01);
                float d10 = f2sum(q10), d11 = f2sum(q11);
                d00 += __shfl_xor_sync(0xffffffffu, d00, 1);
                d01 += __shfl_xor_sync(0xffffffffu, d01, 1);
                d10 += __shfl_xor_sync(0xffffffffu, d10, 1);
                d11 += __shfl_xor_sync(0xffffffffu, d11, 1);

                float z0 = fmaxf(d00 + b1A, 0.f) * w2A
                         + fmaxf(d01 + b1B, 0.f) * w2B;
                float z1 = fmaxf(d10 + b1A, 0.f) * w2A
                         + fmaxf(d11 + b1B, 0.f) * w2B;
                // reduce over oo-bits (even/odd lane parities hold copies)
#pragma unroll
                for (int off = 2; off <= 16; off <<= 1) {
                    z0 += __shfl_xor_sync(0xffffffffu, z0, off);
                    z1 += __shfl_xor_sync(0xffffffffu, z1, off);
                }
                if (lane == 0)
                    red[cur ^ 1][rp][ooh] = make_float2(z0, z1);
            }
            __syncthreads();
            cur ^= 1;
        }

        if (ft < 4) {
            const int r = ft;
            float2 v0 = red[cur][r >> 1][0];
            float2 v1 = red[cur][r >> 1][1];
            float s = (r & 1) ? (v0.y + v1.y) : (v0.x + v1.x);
            out[(size_t)(row0 + r) * T_ + (T_ - 1)] = sigmoid_fast(s + b2);
        }
    }
}

// ---------------------------------------------------------------------------

extern "C" void kernel_launch(void* const* d_in, const int* in_sizes, int n_in,
                              void* d_out, int out_size)
{
    const float* x     = (const float*)d_in[0];
    const float* W_ih  = (const float*)d_in[1];
    const float* W_hh  = (const float*)d_in[2];
    const float* b_ih  = (const float*)d_in[3];
    const float* b_hh  = (const float*)d_in[4];
    const float* fc1_w = (const float*)d_in[5];
    const float* fc1_b = (const float*)d_in[6];
    const float* fc2_w = (const float*)d_in[7];
    const float* fc2_b = (const float*)d_in[8];
    float* out = (float*)d_out;

    xp_kernel<<<(B_ * T_) / 256, 256>>>(x, W_ih, b_ih, b_hh);
    rnn_fused<<<128, NT>>>(W_hh, fc1_w, fc1_b, fc2_w, fc2_b, out);
}